// round 2
// baseline (speedup 1.0000x reference)
#include <cuda_runtime.h>
#include <math.h>

#define SEQ 2048
#define DMODEL 1024
#define NHEAD 16
#define DK 64
#define BHEADS 32
#define MROWS 4096   // B*S

// ---------------- device scratch (no allocations allowed) ----------------
__device__ float g_qp[(size_t)MROWS * DMODEL];
__device__ float g_kp[(size_t)MROWS * DMODEL];
__device__ float g_vp[(size_t)MROWS * DMODEL];
__device__ float g_ao[(size_t)MROWS * DMODEL];
__device__ float g_x [(size_t)MROWS * DMODEL];
__device__ float g_wu[(size_t)BHEADS * SEQ * SEQ];   // unnormalized exp(scores)
__device__ float g_den[(size_t)BHEADS * SEQ];        // softmax denominators

// ---------------- helpers ----------------
#define FMA88(acc, a0, a1, b0, b1) do {                                      \
    float _a[8] = {a0.x,a0.y,a0.z,a0.w,a1.x,a1.y,a1.z,a1.w};                 \
    float _b[8] = {b0.x,b0.y,b0.z,b0.w,b1.x,b1.y,b1.z,b1.w};                 \
    _Pragma("unroll")                                                        \
    for (int _i = 0; _i < 8; _i++) {                                         \
        _Pragma("unroll")                                                    \
        for (int _j = 0; _j < 8; _j++) acc[_i][_j] += _a[_i] * _b[_j];       \
    }                                                                        \
} while (0)

__global__ void init_den_kernel() {
    int i = blockIdx.x * blockDim.x + threadIdx.x;
    if (i < BHEADS * SEQ) g_den[i] = 0.0f;
}

// ---------------- C = A @ W^T + bias (+res). Tile 128x128, BK=16 ----------------
// MODE 0: projections (A external, out = g_qp/g_kp/g_vp by out_sel)
// MODE 1: out-proj (A = g_ao, res external, out = g_x)
template<int MODE>
__global__ __launch_bounds__(256) void gemm_abt(
    const float* __restrict__ A_ext, const float* __restrict__ W,
    const float* __restrict__ bias, const float* __restrict__ res,
    int out_sel, int K, int N)
{
    __shared__ float As[16][132];
    __shared__ float Bs[16][132];
    const int tid = threadIdx.x;
    const int tx = tid & 15, ty = tid >> 4;
    const int row0 = blockIdx.y * 128, col0 = blockIdx.x * 128;

    const float* A = (MODE == 1) ? g_ao : A_ext;
    float* C;
    if (MODE == 1) C = g_x;
    else C = (out_sel == 0) ? g_qp : (out_sel == 1) ? g_kp : g_vp;

    float acc[8][8];
#pragma unroll
    for (int i = 0; i < 8; i++)
#pragma unroll
        for (int j = 0; j < 8; j++) acc[i][j] = 0.0f;

    for (int k0 = 0; k0 < K; k0 += 16) {
#pragma unroll
        for (int p = 0; p < 2; p++) {
            int fi = tid + 256 * p;
            int r = fi >> 2;
            int cg = (fi & 3) << 2;
            float4 av = *(const float4*)(A + (size_t)(row0 + r) * K + k0 + cg);
            As[cg + 0][r] = av.x; As[cg + 1][r] = av.y;
            As[cg + 2][r] = av.z; As[cg + 3][r] = av.w;
            float4 bv = *(const float4*)(W + (size_t)(col0 + r) * K + k0 + cg);
            Bs[cg + 0][r] = bv.x; Bs[cg + 1][r] = bv.y;
            Bs[cg + 2][r] = bv.z; Bs[cg + 3][r] = bv.w;
        }
        __syncthreads();
#pragma unroll
        for (int kk = 0; kk < 16; kk++) {
            float4 a0 = *(const float4*)&As[kk][ty * 8];
            float4 a1 = *(const float4*)&As[kk][ty * 8 + 4];
            float4 b0 = *(const float4*)&Bs[kk][tx * 8];
            float4 b1 = *(const float4*)&Bs[kk][tx * 8 + 4];
            FMA88(acc, a0, a1, b0, b1);
        }
        __syncthreads();
    }

#pragma unroll
    for (int i = 0; i < 8; i++) {
        int r = row0 + ty * 8 + i;
#pragma unroll
        for (int j = 0; j < 8; j++) {
            int c = col0 + tx * 8 + j;
            float vv = acc[i][j] + bias[c];
            if (MODE == 1) vv += res[(size_t)r * N + c];
            C[(size_t)r * N + c] = vv;
        }
    }
}

// ---------------- scores: e = exp((qp.kp^T)/32) with mask; row-sum atomics ----------------
// mask arrives as a 32-bit type (bool converted to int32 or float32 by the
// harness) — "nonzero 32-bit word" == masked covers both encodings.
__global__ __launch_bounds__(256) void scores_kernel(const int* __restrict__ mask)
{
    const int bh = blockIdx.z;
    const int b = bh >> 4, h = bh & 15;
    const int q0 = blockIdx.y * 128, k0 = blockIdx.x * 128;
    const float* Abase = g_qp + (size_t)b * SEQ * DMODEL + h * DK;
    const float* Bbase = g_kp + (size_t)b * SEQ * DMODEL + h * DK;

    __shared__ float As[16][132];
    __shared__ float Bs[16][132];
    __shared__ float rowsum[128];

    const int tid = threadIdx.x;
    const int tx = tid & 15, ty = tid >> 4;
    if (tid < 128) rowsum[tid] = 0.0f;

    float acc[8][8];
#pragma unroll
    for (int i = 0; i < 8; i++)
#pragma unroll
        for (int j = 0; j < 8; j++) acc[i][j] = 0.0f;

    for (int d0 = 0; d0 < DK; d0 += 16) {
#pragma unroll
        for (int p = 0; p < 2; p++) {
            int fi = tid + 256 * p;
            int r = fi >> 2;
            int cg = (fi & 3) << 2;
            float4 av = *(const float4*)(Abase + (size_t)(q0 + r) * DMODEL + d0 + cg);
            As[cg + 0][r] = av.x; As[cg + 1][r] = av.y;
            As[cg + 2][r] = av.z; As[cg + 3][r] = av.w;
            float4 bv = *(const float4*)(Bbase + (size_t)(k0 + r) * DMODEL + d0 + cg);
            Bs[cg + 0][r] = bv.x; Bs[cg + 1][r] = bv.y;
            Bs[cg + 2][r] = bv.z; Bs[cg + 3][r] = bv.w;
        }
        __syncthreads();
#pragma unroll
        for (int kk = 0; kk < 16; kk++) {
            float4 a0 = *(const float4*)&As[kk][ty * 8];
            float4 a1 = *(const float4*)&As[kk][ty * 8 + 4];
            float4 b0 = *(const float4*)&Bs[kk][tx * 8];
            float4 b1 = *(const float4*)&Bs[kk][tx * 8 + 4];
            FMA88(acc, a0, a1, b0, b1);
        }
        __syncthreads();
    }

    // mask batch index quirk: tile(mask,(16,1,1)) against bh = b*16+h  =>  bh % 2
    const int* mrow = mask + (size_t)(bh & 1) * SEQ * SEQ;
    const float inv = 0.03125f; // 1/sqrt(1024)

#pragma unroll
    for (int i = 0; i < 8; i++) {
        int r = q0 + ty * 8 + i;
        const int* mp = mrow + (size_t)r * SEQ + k0 + tx * 8;
        int4 m0 = *(const int4*)(mp);
        int4 m1 = *(const int4*)(mp + 4);
        int mflag[8] = {m0.x, m0.y, m0.z, m0.w, m1.x, m1.y, m1.z, m1.w};
        float e[8];
        float rs = 0.0f;
#pragma unroll
        for (int j = 0; j < 8; j++) {
            float s = acc[i][j] * inv;
            float ev = (mflag[j] != 0) ? 0.0f : expf(s);
            e[j] = ev;
            rs += ev;
        }
        float* wrow = g_wu + ((size_t)bh * SEQ + r) * SEQ + k0 + tx * 8;
        *(float4*)(wrow)     = make_float4(e[0], e[1], e[2], e[3]);
        *(float4*)(wrow + 4) = make_float4(e[4], e[5], e[6], e[7]);
        atomicAdd(&rowsum[ty * 8 + i], rs);
    }
    __syncthreads();
    if (tid < 128)
        atomicAdd(&g_den[(size_t)bh * SEQ + q0 + tid], rowsum[tid]);
}

// ---------------- AV: out = softmax(w) @ vp ; also writes normalized w ----------------
__global__ __launch_bounds__(128) void av_kernel(float* __restrict__ wout)
{
    const int bh = blockIdx.y;
    const int b = bh >> 4, h = bh & 15;
    const int q0 = blockIdx.x * 128;

    __shared__ float Ws[16][132];
    __shared__ float Vs[16][68];
    __shared__ float rden[128];

    const int tid = threadIdx.x;
    const int tx = tid & 7, ty = tid >> 3;

    if (tid < 128) rden[tid] = 1.0f / g_den[(size_t)bh * SEQ + q0 + tid];
    __syncthreads();

    float acc[8][8];
#pragma unroll
    for (int i = 0; i < 8; i++)
#pragma unroll
        for (int j = 0; j < 8; j++) acc[i][j] = 0.0f;

    const float* Wb = g_wu + (size_t)bh * SEQ * SEQ;
    float* WOb = wout ? wout + (size_t)bh * SEQ * SEQ : (float*)0;
    const float* Vb = g_vp + (size_t)b * SEQ * DMODEL + h * DK;

    for (int k0 = 0; k0 < SEQ; k0 += 16) {
        // W chunk [128 q][16 k], normalize on the fly, write w output, store transposed
#pragma unroll
        for (int p = 0; p < 4; p++) {
            int fi = tid + 128 * p;
            int r = fi >> 2;
            int cg = (fi & 3) << 2;
            float4 wv = *(const float4*)(Wb + (size_t)(q0 + r) * SEQ + k0 + cg);
            float sc = rden[r];
            wv.x *= sc; wv.y *= sc; wv.z *= sc; wv.w *= sc;
            if (WOb) *(float4*)(WOb + (size_t)(q0 + r) * SEQ + k0 + cg) = wv;
            Ws[cg + 0][r] = wv.x; Ws[cg + 1][r] = wv.y;
            Ws[cg + 2][r] = wv.z; Ws[cg + 3][r] = wv.w;
        }
        // V chunk [16 k][64 d]
#pragma unroll
        for (int p = 0; p < 2; p++) {
            int fi = tid + 128 * p;
            int kr = fi >> 4;
            int cg = (fi & 15) << 2;
            float4 vv = *(const float4*)(Vb + (size_t)(k0 + kr) * DMODEL + cg);
            *(float4*)&Vs[kr][cg] = vv;
        }
        __syncthreads();
#pragma unroll
        for (int kk = 0; kk < 16; kk++) {
            float4 a0 = *(const float4*)&Ws[kk][ty * 8];
            float4 a1 = *(const float4*)&Ws[kk][ty * 8 + 4];
            float4 b0 = *(const float4*)&Vs[kk][tx * 8];
            float4 b1 = *(const float4*)&Vs[kk][tx * 8 + 4];
            FMA88(acc, a0, a1, b0, b1);
        }
        __syncthreads();
    }

#pragma unroll
    for (int i = 0; i < 8; i++) {
        int r = q0 + ty * 8 + i;
        float* orow = g_ao + ((size_t)(b * SEQ + r)) * DMODEL + h * DK + tx * 8;
        *(float4*)(orow)     = make_float4(acc[i][0], acc[i][1], acc[i][2], acc[i][3]);
        *(float4*)(orow + 4) = make_float4(acc[i][4], acc[i][5], acc[i][6], acc[i][7]);
    }
}

// ---------------- layernorm over g_x rows -> out ----------------
__global__ __launch_bounds__(256) void ln_kernel(
    const float* __restrict__ gamma, const float* __restrict__ beta,
    float* __restrict__ out)
{
    const int row = blockIdx.x;
    const int tid = threadIdx.x;
    const float* xr = g_x + (size_t)row * DMODEL;

    float4 xv = ((const float4*)xr)[tid];
    float s = xv.x + xv.y + xv.z + xv.w;
    float q = xv.x * xv.x + xv.y * xv.y + xv.z * xv.z + xv.w * xv.w;

#pragma unroll
    for (int off = 16; off > 0; off >>= 1) {
        s += __shfl_xor_sync(0xffffffffu, s, off);
        q += __shfl_xor_sync(0xffffffffu, q, off);
    }
    __shared__ float sh1[8], sh2[8];
    __shared__ float smu, srstd;
    int warp = tid >> 5, lane = tid & 31;
    if (lane == 0) { sh1[warp] = s; sh2[warp] = q; }
    __syncthreads();
    if (tid == 0) {
        float S = 0.0f, Q = 0.0f;
#pragma unroll
        for (int w = 0; w < 8; w++) { S += sh1[w]; Q += sh2[w]; }
        float mu = S * (1.0f / DMODEL);
        float var = Q * (1.0f / DMODEL) - mu * mu;
        smu = mu;
        srstd = rsqrtf(var + 1e-6f);
    }
    __syncthreads();
    float mu = smu, rstd = srstd;

    float4 gv = ((const float4*)gamma)[tid];
    float4 bv = ((const float4*)beta)[tid];
    float4 ov;
    ov.x = (xv.x - mu) * rstd * gv.x + bv.x;
    ov.y = (xv.y - mu) * rstd * gv.y + bv.y;
    ov.z = (xv.z - mu) * rstd * gv.z + bv.z;
    ov.w = (xv.w - mu) * rstd * gv.w + bv.w;
    ((float4*)(out + (size_t)row * DMODEL))[tid] = ov;
}

// ---------------- launch ----------------
extern "C" void kernel_launch(void* const* d_in, const int* in_sizes, int n_in,
                              void* d_out, int out_size)
{
    const float* q    = (const float*)d_in[0];
    const float* k    = (const float*)d_in[1];
    const float* v    = (const float*)d_in[2];
    const int*   mask = (const int*)d_in[3];
    const float* Wq   = (const float*)d_in[4];
    const float* bq   = (const float*)d_in[5];
    const float* Wout = (const float*)d_in[6];
    const float* bout = (const float*)d_in[7];
    const float* gamma = (const float*)d_in[8];
    const float* beta  = (const float*)d_in[9];

    float* outp = (float*)d_out;
    float* wptr = (float*)0;
    const long long need = (long long)MROWS * DMODEL + (long long)BHEADS * SEQ * SEQ;
    if ((long long)out_size >= need) wptr = outp + (size_t)MROWS * DMODEL;

    init_den_kernel<<<64, 1024>>>();

    dim3 gproj(DMODEL / 128, MROWS / 128);  // (8, 32)
    gemm_abt<0><<<gproj, 256>>>(q, Wq, bq, (const float*)0, 0, DMODEL, DMODEL);
    gemm_abt<0><<<gproj, 256>>>(k, Wq, bq, (const float*)0, 1, DMODEL, DMODEL);
    gemm_abt<0><<<gproj, 256>>>(v, Wq, bq, (const float*)0, 2, DMODEL, DMODEL);

    dim3 gsc(SEQ / 128, SEQ / 128, BHEADS);  // (16, 16, 32)
    scores_kernel<<<gsc, 256>>>(mask);

    dim3 gav(SEQ / 128, BHEADS);  // (16, 32)
    av_kernel<<<gav, 128>>>(wptr);

    gemm_abt<1><<<gproj, 256>>>((const float*)0, Wout, bout, q, 3, DMODEL, DMODEL);

    ln_kernel<<<MROWS, 256>>>(gamma, beta, outp);
}

// round 4
// speedup vs baseline: 2.0589x; 2.0589x over previous
#include <cuda_runtime.h>
#include <cstdint>
#include <math.h>

#define SEQ 2048
#define DMODEL 1024
#define NHEAD 16
#define DK 64
#define BHEADS 32
#define MROWS 4096   // B*S
#define KPAD 20      // 16 k-floats + 4 pad

// ---------------- device scratch (no allocations allowed) ----------------
__device__ float g_qp[(size_t)MROWS * DMODEL];
__device__ float g_kp[(size_t)MROWS * DMODEL];
__device__ float g_vp[(size_t)MROWS * DMODEL];
__device__ float g_ao[(size_t)MROWS * DMODEL];
__device__ float g_x [(size_t)MROWS * DMODEL];
__device__ float g_wu[(size_t)BHEADS * SEQ * SEQ];   // unnormalized exp(scores)
__device__ float g_den[(size_t)BHEADS * SEQ];        // softmax denominators

// ==================== helpers ====================
__device__ __forceinline__ uint32_t f2tf32(float x) {
    uint32_t r;
    asm("cvt.rna.tf32.f32 %0, %1;" : "=r"(r) : "f"(x));
    return r;
}

// m16n8k8 tf32 mma: D += A @ B ; A row-major frag, B col-major frag
__device__ __forceinline__ void mma8(float* c, const uint32_t* a, const uint32_t* b) {
    asm volatile(
        "mma.sync.aligned.m16n8k8.row.col.f32.tf32.tf32.f32 "
        "{%0,%1,%2,%3}, {%4,%5,%6,%7}, {%8,%9}, {%0,%1,%2,%3};"
        : "+f"(c[0]), "+f"(c[1]), "+f"(c[2]), "+f"(c[3])
        : "r"(a[0]), "r"(a[1]), "r"(a[2]), "r"(a[3]), "r"(b[0]), "r"(b[1]));
}

// FFMA-only exp: exp(s) = 2^(s*log2e); |s| < ~4 here. rel err ~3e-6.
__device__ __forceinline__ float fexp(float s) {
    float y = s * 1.4426950408889634f;
    float r = y + 12582912.0f;                    // round-to-nearest-int magic
    int   n = __float_as_int(r) - 0x4B400000;
    float f = y - (r - 12582912.0f);              // f in [-0.5, 0.5]
    float p = 1.3333558e-3f;                      // 2^f Taylor deg-5
    p = fmaf(p, f, 9.6181291e-3f);
    p = fmaf(p, f, 5.5504109e-2f);
    p = fmaf(p, f, 2.4022651e-1f);
    p = fmaf(p, f, 6.9314718e-1f);
    p = fmaf(p, f, 1.0f);
    return __int_as_float(__float_as_int(p) + (n << 23));
}

__global__ void init_den_kernel() {
    int i = blockIdx.x * blockDim.x + threadIdx.x;
    if (i < BHEADS * SEQ) g_den[i] = 0.0f;
}

// ==================== tf32 mma GEMM: C = A @ W^T + bias (+res) ====================
// CTA 128x128, BK=16, 8 warps in 2x4 (warp tile 64x32). Smem layout [row][KPAD].
// MODE 0: projections (A external, out by out_sel). MODE 1: out-proj (+res -> g_x)
template<int MODE>
__global__ __launch_bounds__(256) void gemm_mma(
    const float* __restrict__ A_ext, const float* __restrict__ W,
    const float* __restrict__ bias, const float* __restrict__ res, int out_sel)
{
    __shared__ float As[128 * KPAD];
    __shared__ float Bs[128 * KPAD];
    const int tid = threadIdx.x, lane = tid & 31, wid = tid >> 5;
    const int gid = lane >> 2, t4 = lane & 3;
    const int wrow = (wid & 1) * 64, wcol = (wid >> 1) * 32;
    const int row0 = blockIdx.y * 128, col0 = blockIdx.x * 128;

    const float* A = (MODE == 1) ? g_ao : A_ext;
    float* C = (MODE == 1) ? g_x : (out_sel == 0 ? g_qp : out_sel == 1 ? g_kp : g_vp);

    const int lr = tid >> 2;          // 0..63 (p adds 64)
    const int lcg = (tid & 3) << 2;   // 0,4,8,12

    float acc[4][4][4];
#pragma unroll
    for (int a = 0; a < 4; a++)
#pragma unroll
        for (int b = 0; b < 4; b++)
#pragma unroll
            for (int c = 0; c < 4; c++) acc[a][b][c] = 0.0f;

    float4 ra[2], rb[2];
#pragma unroll
    for (int p = 0; p < 2; p++) {
        ra[p] = *(const float4*)(A + (size_t)(row0 + lr + 64 * p) * DMODEL + lcg);
        rb[p] = *(const float4*)(W + (size_t)(col0 + lr + 64 * p) * DMODEL + lcg);
    }

    for (int i = 0; i < DMODEL / 16; i++) {
#pragma unroll
        for (int p = 0; p < 2; p++) {
            int r = lr + 64 * p;
            uint32_t* pa = (uint32_t*)&As[r * KPAD + lcg];
            pa[0] = f2tf32(ra[p].x); pa[1] = f2tf32(ra[p].y);
            pa[2] = f2tf32(ra[p].z); pa[3] = f2tf32(ra[p].w);
            uint32_t* pb = (uint32_t*)&Bs[r * KPAD + lcg];
            pb[0] = f2tf32(rb[p].x); pb[1] = f2tf32(rb[p].y);
            pb[2] = f2tf32(rb[p].z); pb[3] = f2tf32(rb[p].w);
        }
        __syncthreads();
        if (i + 1 < DMODEL / 16) {
            int k0 = (i + 1) * 16;
#pragma unroll
            for (int p = 0; p < 2; p++) {
                ra[p] = *(const float4*)(A + (size_t)(row0 + lr + 64 * p) * DMODEL + k0 + lcg);
                rb[p] = *(const float4*)(W + (size_t)(col0 + lr + 64 * p) * DMODEL + k0 + lcg);
            }
        }
#pragma unroll
        for (int ks = 0; ks < 16; ks += 8) {
            uint32_t af[4][4], bf[4][2];
#pragma unroll
            for (int mt = 0; mt < 4; mt++) {
                const uint32_t* base = (const uint32_t*)&As[(wrow + mt * 16) * KPAD];
                af[mt][0] = base[(gid    ) * KPAD + ks + t4];
                af[mt][1] = base[(gid + 8) * KPAD + ks + t4];
                af[mt][2] = base[(gid    ) * KPAD + ks + t4 + 4];
                af[mt][3] = base[(gid + 8) * KPAD + ks + t4 + 4];
            }
#pragma unroll
            for (int nt = 0; nt < 4; nt++) {
                const uint32_t* base = (const uint32_t*)&Bs[(wcol + nt * 8) * KPAD];
                bf[nt][0] = base[gid * KPAD + ks + t4];
                bf[nt][1] = base[gid * KPAD + ks + t4 + 4];
            }
#pragma unroll
            for (int mt = 0; mt < 4; mt++)
#pragma unroll
                for (int nt = 0; nt < 4; nt++) mma8(acc[mt][nt], af[mt], bf[nt]);
        }
        __syncthreads();
    }

#pragma unroll
    for (int mt = 0; mt < 4; mt++) {
#pragma unroll
        for (int nt = 0; nt < 4; nt++) {
            int r = row0 + wrow + mt * 16 + gid;
            int c = col0 + wcol + nt * 8 + t4 * 2;
            float2 bv = *(const float2*)(bias + c);
            float2 o0 = { acc[mt][nt][0] + bv.x, acc[mt][nt][1] + bv.y };
            float2 o1 = { acc[mt][nt][2] + bv.x, acc[mt][nt][3] + bv.y };
            if (MODE == 1) {
                float2 r0 = *(const float2*)(res + (size_t)r * DMODEL + c);
                float2 r1 = *(const float2*)(res + (size_t)(r + 8) * DMODEL + c);
                o0.x += r0.x; o0.y += r0.y; o1.x += r1.x; o1.y += r1.y;
            }
            *(float2*)(C + (size_t)r * DMODEL + c) = o0;
            *(float2*)(C + (size_t)(r + 8) * DMODEL + c) = o1;
        }
    }
}

// ==================== scores: e = exp((qp.kp^T)/32), mask, row sums ====================
__global__ __launch_bounds__(256) void scores_mma(const int* __restrict__ mask)
{
    __shared__ float As[128 * KPAD];
    __shared__ float Bs[128 * KPAD];
    __shared__ float rowsum[128];

    const int bh = blockIdx.z, b = bh >> 4, h = bh & 15;
    const int q0 = blockIdx.y * 128, k0 = blockIdx.x * 128;
    const float* Ab = g_qp + (size_t)b * SEQ * DMODEL + h * DK;
    const float* Bb = g_kp + (size_t)b * SEQ * DMODEL + h * DK;

    const int tid = threadIdx.x, lane = tid & 31, wid = tid >> 5;
    const int gid = lane >> 2, t4 = lane & 3;
    const int wrow = (wid & 1) * 64, wcol = (wid >> 1) * 32;
    const int lr = tid >> 2, lcg = (tid & 3) << 2;

    if (tid < 128) rowsum[tid] = 0.0f;

    float acc[4][4][4];
#pragma unroll
    for (int a = 0; a < 4; a++)
#pragma unroll
        for (int c = 0; c < 4; c++)
#pragma unroll
            for (int d = 0; d < 4; d++) acc[a][c][d] = 0.0f;

    float4 ra[2], rb[2];
#pragma unroll
    for (int p = 0; p < 2; p++) {
        ra[p] = *(const float4*)(Ab + (size_t)(q0 + lr + 64 * p) * DMODEL + lcg);
        rb[p] = *(const float4*)(Bb + (size_t)(k0 + lr + 64 * p) * DMODEL + lcg);
    }

    for (int i = 0; i < DK / 16; i++) {
#pragma unroll
        for (int p = 0; p < 2; p++) {
            int r = lr + 64 * p;
            uint32_t* pa = (uint32_t*)&As[r * KPAD + lcg];
            pa[0] = f2tf32(ra[p].x); pa[1] = f2tf32(ra[p].y);
            pa[2] = f2tf32(ra[p].z); pa[3] = f2tf32(ra[p].w);
            uint32_t* pb = (uint32_t*)&Bs[r * KPAD + lcg];
            pb[0] = f2tf32(rb[p].x); pb[1] = f2tf32(rb[p].y);
            pb[2] = f2tf32(rb[p].z); pb[3] = f2tf32(rb[p].w);
        }
        __syncthreads();
        if (i + 1 < DK / 16) {
            int d0 = (i + 1) * 16;
#pragma unroll
            for (int p = 0; p < 2; p++) {
                ra[p] = *(const float4*)(Ab + (size_t)(q0 + lr + 64 * p) * DMODEL + d0 + lcg);
                rb[p] = *(const float4*)(Bb + (size_t)(k0 + lr + 64 * p) * DMODEL + d0 + lcg);
            }
        }
#pragma unroll
        for (int ks = 0; ks < 16; ks += 8) {
            uint32_t af[4][4], bf[4][2];
#pragma unroll
            for (int mt = 0; mt < 4; mt++) {
                const uint32_t* base = (const uint32_t*)&As[(wrow + mt * 16) * KPAD];
                af[mt][0] = base[(gid    ) * KPAD + ks + t4];
                af[mt][1] = base[(gid + 8) * KPAD + ks + t4];
                af[mt][2] = base[(gid    ) * KPAD + ks + t4 + 4];
                af[mt][3] = base[(gid + 8) * KPAD + ks + t4 + 4];
            }
#pragma unroll
            for (int nt = 0; nt < 4; nt++) {
                const uint32_t* base = (const uint32_t*)&Bs[(wcol + nt * 8) * KPAD];
                bf[nt][0] = base[gid * KPAD + ks + t4];
                bf[nt][1] = base[gid * KPAD + ks + t4 + 4];
            }
#pragma unroll
            for (int mt = 0; mt < 4; mt++)
#pragma unroll
                for (int nt = 0; nt < 4; nt++) mma8(acc[mt][nt], af[mt], bf[nt]);
        }
        __syncthreads();
    }

    // mask batch quirk: tile(mask,(16,1,1)) vs bh=b*16+h => index bh%2
    const int* mrow = mask + (size_t)(bh & 1) * SEQ * SEQ;
    const float inv = 0.03125f;

#pragma unroll
    for (int mt = 0; mt < 4; mt++) {
#pragma unroll
        for (int half = 0; half < 2; half++) {
            int r = q0 + wrow + mt * 16 + gid + half * 8;
            float rsum = 0.0f;
#pragma unroll
            for (int nt = 0; nt < 4; nt++) {
                int c = k0 + wcol + nt * 8 + t4 * 2;
                int2 m = *(const int2*)(mrow + (size_t)r * SEQ + c);
                float e0 = m.x ? 0.0f : fexp(acc[mt][nt][half * 2 + 0] * inv);
                float e1 = m.y ? 0.0f : fexp(acc[mt][nt][half * 2 + 1] * inv);
                float2 ev = { e0, e1 };
                *(float2*)(g_wu + ((size_t)bh * SEQ + r) * SEQ + c) = ev;
                rsum += e0 + e1;
            }
            rsum += __shfl_xor_sync(0xffffffffu, rsum, 1);
            rsum += __shfl_xor_sync(0xffffffffu, rsum, 2);
            if (t4 == 0)
                atomicAdd(&rowsum[wrow + mt * 16 + gid + half * 8], rsum);
        }
    }
    __syncthreads();
    if (tid < 128)
        atomicAdd(&g_den[(size_t)bh * SEQ + q0 + tid], rowsum[tid]);
}

// ==================== AV: out = softmax(w) @ vp; writes normalized w ====================
// CTA: 128 q x 64 d, 256 threads = 8 warps in 4x2 (warp tile 32x32), K=2048, BK=16.
__global__ __launch_bounds__(256) void av_mma(float* __restrict__ wout)
{
    __shared__ float Ws[128 * KPAD];   // [q][k] tf32
    __shared__ float Vs[16 * 68];      // [k][d] tf32
    __shared__ float rden[128];

    const int bh = blockIdx.y, b = bh >> 4, h = bh & 15;
    const int q0 = blockIdx.x * 128;

    const int tid = threadIdx.x, lane = tid & 31, wid = tid >> 5;
    const int gid = lane >> 2, t4 = lane & 3;
    const int wrow = (wid & 3) * 32, wcol = (wid >> 2) * 32;
    const int lr = tid >> 2, lcg = (tid & 3) << 2;
    const int vr = tid >> 4, vc = (tid & 15) << 2;

    if (tid < 128) rden[tid] = 1.0f / g_den[(size_t)bh * SEQ + q0 + tid];
    __syncthreads();

    float acc[2][4][4];
#pragma unroll
    for (int a = 0; a < 2; a++)
#pragma unroll
        for (int c = 0; c < 4; c++)
#pragma unroll
            for (int d = 0; d < 4; d++) acc[a][c][d] = 0.0f;

    const float* Wb = g_wu + (size_t)bh * SEQ * SEQ;
    float* WOb = wout ? wout + (size_t)bh * SEQ * SEQ : (float*)0;
    const float* Vb = g_vp + (size_t)b * SEQ * DMODEL + h * DK;

    float4 rw[2], rv;
#pragma unroll
    for (int p = 0; p < 2; p++)
        rw[p] = *(const float4*)(Wb + (size_t)(q0 + lr + 64 * p) * SEQ + lcg);
    rv = *(const float4*)(Vb + (size_t)vr * DMODEL + vc);

    for (int i = 0; i < SEQ / 16; i++) {
        const int k0 = i * 16;
#pragma unroll
        for (int p = 0; p < 2; p++) {
            int r = lr + 64 * p;
            float sc = rden[r];
            float4 w = rw[p];
            w.x *= sc; w.y *= sc; w.z *= sc; w.w *= sc;
            if (WOb) *(float4*)(WOb + (size_t)(q0 + r) * SEQ + k0 + lcg) = w;
            uint32_t* pw = (uint32_t*)&Ws[r * KPAD + lcg];
            pw[0] = f2tf32(w.x); pw[1] = f2tf32(w.y);
            pw[2] = f2tf32(w.z); pw[3] = f2tf32(w.w);
        }
        {
            uint32_t* pv = (uint32_t*)&Vs[vr * 68 + vc];
            pv[0] = f2tf32(rv.x); pv[1] = f2tf32(rv.y);
            pv[2] = f2tf32(rv.z); pv[3] = f2tf32(rv.w);
        }
        __syncthreads();
        if (i + 1 < SEQ / 16) {
            int kn = k0 + 16;
#pragma unroll
            for (int p = 0; p < 2; p++)
                rw[p] = *(const float4*)(Wb + (size_t)(q0 + lr + 64 * p) * SEQ + kn + lcg);
            rv = *(const float4*)(Vb + (size_t)(kn + vr) * DMODEL + vc);
        }
#pragma unroll
        for (int ks = 0; ks < 16; ks += 8) {
            uint32_t af[2][4], bf[4][2];
#pragma unroll
            for (int mt = 0; mt < 2; mt++) {
                const uint32_t* base = (const uint32_t*)&Ws[(wrow + mt * 16) * KPAD];
                af[mt][0] = base[(gid    ) * KPAD + ks + t4];
                af[mt][1] = base[(gid + 8) * KPAD + ks + t4];
                af[mt][2] = base[(gid    ) * KPAD + ks + t4 + 4];
                af[mt][3] = base[(gid + 8) * KPAD + ks + t4 + 4];
            }
#pragma unroll
            for (int nt = 0; nt < 4; nt++) {
                bf[nt][0] = ((const uint32_t*)Vs)[(ks + t4    ) * 68 + wcol + nt * 8 + gid];
                bf[nt][1] = ((const uint32_t*)Vs)[(ks + t4 + 4) * 68 + wcol + nt * 8 + gid];
            }
#pragma unroll
            for (int mt = 0; mt < 2; mt++)
#pragma unroll
                for (int nt = 0; nt < 4; nt++) mma8(acc[mt][nt], af[mt], bf[nt]);
        }
        __syncthreads();
    }

#pragma unroll
    for (int mt = 0; mt < 2; mt++) {
#pragma unroll
        for (int nt = 0; nt < 4; nt++) {
            int r = q0 + wrow + mt * 16 + gid;
            int c = wcol + nt * 8 + t4 * 2;
            float* orow = g_ao + ((size_t)(b * SEQ + r)) * DMODEL + h * DK + c;
            float2 o0 = { acc[mt][nt][0], acc[mt][nt][1] };
            float2 o1 = { acc[mt][nt][2], acc[mt][nt][3] };
            *(float2*)orow = o0;
            *(float2*)(orow + (size_t)8 * DMODEL) = o1;
        }
    }
}

// ---------------- layernorm over g_x rows -> out ----------------
__global__ __launch_bounds__(256) void ln_kernel(
    const float* __restrict__ gamma, const float* __restrict__ beta,
    float* __restrict__ out)
{
    const int row = blockIdx.x;
    const int tid = threadIdx.x;
    const float* xr = g_x + (size_t)row * DMODEL;

    float4 xv = ((const float4*)xr)[tid];
    float s = xv.x + xv.y + xv.z + xv.w;
    float q = xv.x * xv.x + xv.y * xv.y + xv.z * xv.z + xv.w * xv.w;

#pragma unroll
    for (int off = 16; off > 0; off >>= 1) {
        s += __shfl_xor_sync(0xffffffffu, s, off);
        q += __shfl_xor_sync(0xffffffffu, q, off);
    }
    __shared__ float sh1[8], sh2[8];
    __shared__ float smu, srstd;
    int warp = tid >> 5, lane = tid & 31;
    if (lane == 0) { sh1[warp] = s; sh2[warp] = q; }
    __syncthreads();
    if (tid == 0) {
        float S = 0.0f, Q = 0.0f;
#pragma unroll
        for (int w = 0; w < 8; w++) { S += sh1[w]; Q += sh2[w]; }
        float mu = S * (1.0f / DMODEL);
        float var = Q * (1.0f / DMODEL) - mu * mu;
        smu = mu;
        srstd = rsqrtf(var + 1e-6f);
    }
    __syncthreads();
    float mu = smu, rstd = srstd;

    float4 gv = ((const float4*)gamma)[tid];
    float4 bv = ((const float4*)beta)[tid];
    float4 ov;
    ov.x = (xv.x - mu) * rstd * gv.x + bv.x;
    ov.y = (xv.y - mu) * rstd * gv.y + bv.y;
    ov.z = (xv.z - mu) * rstd * gv.z + bv.z;
    ov.w = (xv.w - mu) * rstd * gv.w + bv.w;
    ((float4*)(out + (size_t)row * DMODEL))[tid] = ov;
}

// ---------------- launch ----------------
extern "C" void kernel_launch(void* const* d_in, const int* in_sizes, int n_in,
                              void* d_out, int out_size)
{
    const float* q    = (const float*)d_in[0];
    const float* k    = (const float*)d_in[1];
    const float* v    = (const float*)d_in[2];
    const int*   mask = (const int*)d_in[3];
    const float* Wq   = (const float*)d_in[4];
    const float* bq   = (const float*)d_in[5];
    const float* Wout = (const float*)d_in[6];
    const float* bout = (const float*)d_in[7];
    const float* gamma = (const float*)d_in[8];
    const float* beta  = (const float*)d_in[9];

    float* outp = (float*)d_out;
    float* wptr = (float*)0;
    const long long need = (long long)MROWS * DMODEL + (long long)BHEADS * SEQ * SEQ;
    if ((long long)out_size >= need) wptr = outp + (size_t)MROWS * DMODEL;

    init_den_kernel<<<64, 1024>>>();

    dim3 gproj(DMODEL / 128, MROWS / 128);  // (8, 32)
    gemm_mma<0><<<gproj, 256>>>(q, Wq, bq, (const float*)0, 0);
    gemm_mma<0><<<gproj, 256>>>(k, Wq, bq, (const float*)0, 1);
    gemm_mma<0><<<gproj, 256>>>(v, Wq, bq, (const float*)0, 2);

    dim3 gsc(SEQ / 128, SEQ / 128, BHEADS);  // (16, 16, 32)
    scores_mma<<<gsc, 256>>>(mask);

    dim3 gav(SEQ / 128, BHEADS);  // (16, 32)
    av_mma<<<gav, 256>>>(wptr);

    gemm_mma<1><<<gproj, 256>>>((const float*)0, Wout, bout, q, 3);

    ln_kernel<<<MROWS, 256>>>(gamma, beta, outp);
}

// round 5
// speedup vs baseline: 2.4608x; 1.1953x over previous
#include <cuda_runtime.h>
#include <cstdint>
#include <math.h>

#define SEQ 2048
#define DMODEL 1024
#define NHEAD 16
#define DK 64
#define BHEADS 32
#define MROWS 4096   // B*S

// ---------------- device scratch (no allocations allowed) ----------------
__device__ float g_qp[(size_t)MROWS * DMODEL];
__device__ float g_kp[(size_t)MROWS * DMODEL];
__device__ float g_vp[(size_t)MROWS * DMODEL];
__device__ float g_ao[(size_t)MROWS * DMODEL];
__device__ float g_x [(size_t)MROWS * DMODEL];
__device__ float g_wu[(size_t)BHEADS * SEQ * SEQ];   // unnormalized exp(scores)
__device__ float g_den[(size_t)BHEADS * SEQ];        // softmax denominators

// ==================== helpers ====================
__device__ __forceinline__ uint32_t smem_u32(const void* p) {
    uint32_t a;
    asm("{ .reg .u64 t; cvta.to.shared.u64 t, %1; cvt.u32.u64 %0, t; }"
        : "=r"(a) : "l"(p));
    return a;
}

#define CP_ASYNC16(dst, src) \
    asm volatile("cp.async.cg.shared.global [%0], [%1], 16;" :: "r"(dst), "l"(src))
#define CP_COMMIT() asm volatile("cp.async.commit_group;")
#define CP_WAIT(n)  asm volatile("cp.async.wait_group %0;" :: "n"(n))

// m16n8k8 tf32 mma: D += A @ B ; raw fp32 bits fed as tf32 (HW truncates)
__device__ __forceinline__ void mma8(float* c, const uint32_t* a, const uint32_t* b) {
    asm volatile(
        "mma.sync.aligned.m16n8k8.row.col.f32.tf32.tf32.f32 "
        "{%0,%1,%2,%3}, {%4,%5,%6,%7}, {%8,%9}, {%0,%1,%2,%3};"
        : "+f"(c[0]), "+f"(c[1]), "+f"(c[2]), "+f"(c[3])
        : "r"(a[0]), "r"(a[1]), "r"(a[2]), "r"(a[3]), "r"(b[0]), "r"(b[1]));
}

// FFMA-only exp: exp(s) = 2^(s*log2e). rel err ~3e-6 for |s|<~10.
__device__ __forceinline__ float fexp(float s) {
    float y = s * 1.4426950408889634f;
    float r = y + 12582912.0f;
    int   n = __float_as_int(r) - 0x4B400000;
    float f = y - (r - 12582912.0f);
    float p = 1.3333558e-3f;
    p = fmaf(p, f, 9.6181291e-3f);
    p = fmaf(p, f, 5.5504109e-2f);
    p = fmaf(p, f, 2.4022651e-1f);
    p = fmaf(p, f, 6.9314718e-1f);
    p = fmaf(p, f, 1.0f);
    return __int_as_float(__float_as_int(p) + (n << 23));
}

__global__ void init_den_kernel() {
    int i = blockIdx.x * blockDim.x + threadIdx.x;
    if (i < BHEADS * SEQ) g_den[i] = 0.0f;
}

// ==================== cp.async double-buffered tf32 GEMM ====================
// C = A @ W^T + bias (+res). CTA 128x128, BK=32, 2 stages.
// MODE 0: projections, blockIdx.z selects q/k/v (same W). MODE 1: out-proj + res.
#define GP 36                 // smem row pitch (floats)
#define GSTG (128 * GP)       // 4608 floats per matrix per stage
#define GEMM_SMEM (2 * 2 * GSTG * 4)   // 73728 bytes

template<int MODE>
__global__ __launch_bounds__(256) void gemm_cp(
    const float* __restrict__ Aq, const float* __restrict__ Ak, const float* __restrict__ Av,
    const float* __restrict__ W, const float* __restrict__ bias, const float* __restrict__ res)
{
    extern __shared__ float sm[];
    const int tid = threadIdx.x, lane = tid & 31, wid = tid >> 5;
    const int gid = lane >> 2, t4 = lane & 3;
    const int wrow = (wid & 1) * 64, wcol = (wid >> 1) * 32;
    const int row0 = blockIdx.y * 128, col0 = blockIdx.x * 128;
    const int z = blockIdx.z;

    const float* A = (MODE == 1) ? g_ao : (z == 0 ? Aq : z == 1 ? Ak : Av);
    float* C = (MODE == 1) ? g_x : (z == 0 ? g_qp : z == 1 ? g_kp : g_vp);

    const uint32_t sbase = smem_u32(sm);

    float acc[4][4][4];
#pragma unroll
    for (int a = 0; a < 4; a++)
#pragma unroll
        for (int b = 0; b < 4; b++)
#pragma unroll
            for (int c = 0; c < 4; c++) acc[a][b][c] = 0.0f;

    auto load_stage = [&](int s, int k0) {
        const uint32_t sa = sbase + (uint32_t)(s * 2 * GSTG) * 4;
        const uint32_t sb2 = sa + (uint32_t)GSTG * 4;
#pragma unroll
        for (int p = 0; p < 4; p++) {
            int cc = tid + 256 * p;        // 0..1023
            int row = cc >> 3;
            int c4 = (cc & 7) << 2;
            CP_ASYNC16(sa + (uint32_t)(row * GP + c4) * 4,
                       A + (size_t)(row0 + row) * DMODEL + k0 + c4);
            CP_ASYNC16(sb2 + (uint32_t)(row * GP + c4) * 4,
                       W + (size_t)(col0 + row) * DMODEL + k0 + c4);
        }
        CP_COMMIT();
    };

    load_stage(0, 0);
    load_stage(1, 32);

    for (int i = 0; i < 32; i++) {
        if (i == 31) { CP_WAIT(0); } else { CP_WAIT(1); }
        __syncthreads();
        const float* As = sm + (i & 1) * 2 * GSTG;
        const float* Bs = As + GSTG;
#pragma unroll
        for (int ks = 0; ks < 32; ks += 8) {
            uint32_t af[4][4], bf[4][2];
#pragma unroll
            for (int mt = 0; mt < 4; mt++) {
                const uint32_t* base = (const uint32_t*)&As[(wrow + mt * 16) * GP];
                af[mt][0] = base[(gid    ) * GP + ks + t4];
                af[mt][1] = base[(gid + 8) * GP + ks + t4];
                af[mt][2] = base[(gid    ) * GP + ks + t4 + 4];
                af[mt][3] = base[(gid + 8) * GP + ks + t4 + 4];
            }
#pragma unroll
            for (int nt = 0; nt < 4; nt++) {
                const uint32_t* base = (const uint32_t*)&Bs[(wcol + nt * 8) * GP];
                bf[nt][0] = base[gid * GP + ks + t4];
                bf[nt][1] = base[gid * GP + ks + t4 + 4];
            }
#pragma unroll
            for (int mt = 0; mt < 4; mt++)
#pragma unroll
                for (int nt = 0; nt < 4; nt++) mma8(acc[mt][nt], af[mt], bf[nt]);
        }
        __syncthreads();
        if (i + 2 < 32) load_stage(i & 1, (i + 2) * 32);
    }

#pragma unroll
    for (int mt = 0; mt < 4; mt++) {
#pragma unroll
        for (int nt = 0; nt < 4; nt++) {
            int r = row0 + wrow + mt * 16 + gid;
            int c = col0 + wcol + nt * 8 + t4 * 2;
            float2 bv = *(const float2*)(bias + c);
            float2 o0 = { acc[mt][nt][0] + bv.x, acc[mt][nt][1] + bv.y };
            float2 o1 = { acc[mt][nt][2] + bv.x, acc[mt][nt][3] + bv.y };
            if (MODE == 1) {
                float2 r0 = *(const float2*)(res + (size_t)r * DMODEL + c);
                float2 r1 = *(const float2*)(res + (size_t)(r + 8) * DMODEL + c);
                o0.x += r0.x; o0.y += r0.y; o1.x += r1.x; o1.y += r1.y;
            }
            *(float2*)(C + (size_t)r * DMODEL + c) = o0;
            *(float2*)(C + (size_t)(r + 8) * DMODEL + c) = o1;
        }
    }
}

// ==================== scores: single-shot smem, e = exp(qk/32), mask, sums ====
#define SP 68
#define SCORES_SMEM ((2 * 128 * SP + 128) * 4)   // 70144 bytes

__global__ __launch_bounds__(256) void scores_cp(const int* __restrict__ mask)
{
    extern __shared__ float sm[];
    float* As = sm;
    float* Bs = sm + 128 * SP;
    float* rowsum = Bs + 128 * SP;

    const int bh = blockIdx.z, b = bh >> 4, h = bh & 15;
    const int q0 = blockIdx.y * 128, k0 = blockIdx.x * 128;
    const float* Ab = g_qp + (size_t)b * SEQ * DMODEL + h * DK;
    const float* Bb = g_kp + (size_t)b * SEQ * DMODEL + h * DK;

    const int tid = threadIdx.x, lane = tid & 31, wid = tid >> 5;
    const int gid = lane >> 2, t4 = lane & 3;
    const int wrow = (wid & 1) * 64, wcol = (wid >> 1) * 32;

    const uint32_t abase = smem_u32(As);
    const uint32_t bbase = smem_u32(Bs);

    // whole 128x64 tiles in one async burst
#pragma unroll
    for (int p = 0; p < 8; p++) {
        int cc = tid + 256 * p;            // 0..2047
        int row = cc >> 4;
        int c4 = (cc & 15) << 2;
        CP_ASYNC16(abase + (uint32_t)(row * SP + c4) * 4,
                   Ab + (size_t)(q0 + row) * DMODEL + c4);
        CP_ASYNC16(bbase + (uint32_t)(row * SP + c4) * 4,
                   Bb + (size_t)(k0 + row) * DMODEL + c4);
    }
    CP_COMMIT();

    if (tid < 128) rowsum[tid] = 0.0f;

    float acc[4][4][4];
#pragma unroll
    for (int a = 0; a < 4; a++)
#pragma unroll
        for (int c = 0; c < 4; c++)
#pragma unroll
            for (int d = 0; d < 4; d++) acc[a][c][d] = 0.0f;

    CP_WAIT(0);
    __syncthreads();

#pragma unroll
    for (int ks = 0; ks < 64; ks += 8) {
        uint32_t af[4][4], bf[4][2];
#pragma unroll
        for (int mt = 0; mt < 4; mt++) {
            const uint32_t* base = (const uint32_t*)&As[(wrow + mt * 16) * SP];
            af[mt][0] = base[(gid    ) * SP + ks + t4];
            af[mt][1] = base[(gid + 8) * SP + ks + t4];
            af[mt][2] = base[(gid    ) * SP + ks + t4 + 4];
            af[mt][3] = base[(gid + 8) * SP + ks + t4 + 4];
        }
#pragma unroll
        for (int nt = 0; nt < 4; nt++) {
            const uint32_t* base = (const uint32_t*)&Bs[(wcol + nt * 8) * SP];
            bf[nt][0] = base[gid * SP + ks + t4];
            bf[nt][1] = base[gid * SP + ks + t4 + 4];
        }
#pragma unroll
        for (int mt = 0; mt < 4; mt++)
#pragma unroll
            for (int nt = 0; nt < 4; nt++) mma8(acc[mt][nt], af[mt], bf[nt]);
    }

    // mask batch quirk: tile(mask,(16,1,1)) vs bh=b*16+h => index bh%2
    const int* mrow = mask + (size_t)(bh & 1) * SEQ * SEQ;
    const float inv = 0.03125f;

#pragma unroll
    for (int mt = 0; mt < 4; mt++) {
#pragma unroll
        for (int half = 0; half < 2; half++) {
            int r = q0 + wrow + mt * 16 + gid + half * 8;
            float rsum = 0.0f;
#pragma unroll
            for (int nt = 0; nt < 4; nt++) {
                int c = k0 + wcol + nt * 8 + t4 * 2;
                int2 m = *(const int2*)(mrow + (size_t)r * SEQ + c);
                float e0 = m.x ? 0.0f : fexp(acc[mt][nt][half * 2 + 0] * inv);
                float e1 = m.y ? 0.0f : fexp(acc[mt][nt][half * 2 + 1] * inv);
                float2 ev = { e0, e1 };
                *(float2*)(g_wu + ((size_t)bh * SEQ + r) * SEQ + c) = ev;
                rsum += e0 + e1;
            }
            rsum += __shfl_xor_sync(0xffffffffu, rsum, 1);
            rsum += __shfl_xor_sync(0xffffffffu, rsum, 2);
            if (t4 == 0)
                atomicAdd(&rowsum[wrow + mt * 16 + gid + half * 8], rsum);
        }
    }
    __syncthreads();
    if (tid < 128)
        atomicAdd(&g_den[(size_t)bh * SEQ + q0 + tid], rowsum[tid]);
}

// ==================== AV: out = softmax(w) @ vp; writes normalized w ========
// CTA 128q x 64d, 8 warps 4x2 (warp 32x32), BK=32, 64 iters, V via cp.async.
#define WP 36
#define VPITCH 72
#define WSTG (128 * WP)        // 4608 floats
#define VSTG (32 * VPITCH)     // 2304 floats
#define AV_SMEM ((2 * WSTG + 2 * VSTG + 128) * 4)   // 55808 bytes

__global__ __launch_bounds__(256) void av_cp(float* __restrict__ wout)
{
    extern __shared__ float sm[];
    float* rden = sm + 2 * WSTG + 2 * VSTG;

    const int bh = blockIdx.y, b = bh >> 4, h = bh & 15;
    const int q0 = blockIdx.x * 128;

    const int tid = threadIdx.x, lane = tid & 31, wid = tid >> 5;
    const int gid = lane >> 2, t4 = lane & 3;
    const int wrow = (wid & 3) * 32, wcol = (wid >> 2) * 32;

    const float* Wb = g_wu + (size_t)bh * SEQ * SEQ;
    float* WOb = wout ? wout + (size_t)bh * SEQ * SEQ : (float*)0;
    const float* Vb = g_vp + (size_t)b * SEQ * DMODEL + h * DK;

    const uint32_t sbase = smem_u32(sm);

    if (tid < 128) rden[tid] = 1.0f / g_den[(size_t)bh * SEQ + q0 + tid];
    __syncthreads();

    const int wr = tid >> 1;             // w row this thread handles
    const int wk = (tid & 1) << 4;       // 0 or 16
    const float sc = rden[wr];

    float acc[2][4][4];
#pragma unroll
    for (int a = 0; a < 2; a++)
#pragma unroll
        for (int c = 0; c < 4; c++)
#pragma unroll
            for (int d = 0; d < 4; d++) acc[a][c][d] = 0.0f;

    auto loadV = [&](int s, int k0) {
        const uint32_t vb = sbase + (uint32_t)(2 * WSTG + s * VSTG) * 4;
#pragma unroll
        for (int p = 0; p < 2; p++) {
            int cc = tid + 256 * p;        // 0..511
            int row = cc >> 4;
            int c4 = (cc & 15) << 2;
            CP_ASYNC16(vb + (uint32_t)(row * VPITCH + c4) * 4,
                       Vb + (size_t)(k0 + row) * DMODEL + c4);
        }
        CP_COMMIT();
    };

    float4 rw[4];
#pragma unroll
    for (int j = 0; j < 4; j++)
        rw[j] = *(const float4*)(Wb + (size_t)(q0 + wr) * SEQ + wk + j * 4);
    loadV(0, 0);
    loadV(1, 32);

    for (int i = 0; i < 64; i++) {
        const int s = i & 1;
        const int k0 = i * 32;

        // normalize, write wout, stage into smem (raw fp32 -> tf32 by HW)
        float* WS = sm + s * WSTG;
#pragma unroll
        for (int j = 0; j < 4; j++) {
            float4 w = rw[j];
            w.x *= sc; w.y *= sc; w.z *= sc; w.w *= sc;
            if (WOb) *(float4*)(WOb + (size_t)(q0 + wr) * SEQ + k0 + wk + j * 4) = w;
            *(float4*)&WS[wr * WP + wk + j * 4] = w;
        }
        float4 rwn[4];
        if (i + 1 < 64) {
#pragma unroll
            for (int j = 0; j < 4; j++)
                rwn[j] = *(const float4*)(Wb + (size_t)(q0 + wr) * SEQ + k0 + 32 + wk + j * 4);
        }

        if (i == 63) { CP_WAIT(0); } else { CP_WAIT(1); }
        __syncthreads();

        const float* Ws_ = sm + s * WSTG;
        const float* Vs_ = sm + 2 * WSTG + s * VSTG;
#pragma unroll
        for (int ks = 0; ks < 32; ks += 8) {
            uint32_t af[2][4], bf[4][2];
#pragma unroll
            for (int mt = 0; mt < 2; mt++) {
                const uint32_t* base = (const uint32_t*)&Ws_[(wrow + mt * 16) * WP];
                af[mt][0] = base[(gid    ) * WP + ks + t4];
                af[mt][1] = base[(gid + 8) * WP + ks + t4];
                af[mt][2] = base[(gid    ) * WP + ks + t4 + 4];
                af[mt][3] = base[(gid + 8) * WP + ks + t4 + 4];
            }
#pragma unroll
            for (int nt = 0; nt < 4; nt++) {
                bf[nt][0] = ((const uint32_t*)Vs_)[(ks + t4    ) * VPITCH + wcol + nt * 8 + gid];
                bf[nt][1] = ((const uint32_t*)Vs_)[(ks + t4 + 4) * VPITCH + wcol + nt * 8 + gid];
            }
#pragma unroll
            for (int mt = 0; mt < 2; mt++)
#pragma unroll
                for (int nt = 0; nt < 4; nt++) mma8(acc[mt][nt], af[mt], bf[nt]);
        }
        __syncthreads();
        if (i + 2 < 64) loadV(s, (i + 2) * 32);
#pragma unroll
        for (int j = 0; j < 4; j++) rw[j] = rwn[j];
    }

#pragma unroll
    for (int mt = 0; mt < 2; mt++) {
#pragma unroll
        for (int nt = 0; nt < 4; nt++) {
            int r = q0 + wrow + mt * 16 + gid;
            int c = wcol + nt * 8 + t4 * 2;
            float* orow = g_ao + ((size_t)(b * SEQ + r)) * DMODEL + h * DK + c;
            float2 o0 = { acc[mt][nt][0], acc[mt][nt][1] };
            float2 o1 = { acc[mt][nt][2], acc[mt][nt][3] };
            *(float2*)orow = o0;
            *(float2*)(orow + (size_t)8 * DMODEL) = o1;
        }
    }
}

// ---------------- layernorm over g_x rows -> out ----------------
__global__ __launch_bounds__(256) void ln_kernel(
    const float* __restrict__ gamma, const float* __restrict__ beta,
    float* __restrict__ out)
{
    const int row = blockIdx.x;
    const int tid = threadIdx.x;
    const float* xr = g_x + (size_t)row * DMODEL;

    float4 xv = ((const float4*)xr)[tid];
    float s = xv.x + xv.y + xv.z + xv.w;
    float q = xv.x * xv.x + xv.y * xv.y + xv.z * xv.z + xv.w * xv.w;

#pragma unroll
    for (int off = 16; off > 0; off >>= 1) {
        s += __shfl_xor_sync(0xffffffffu, s, off);
        q += __shfl_xor_sync(0xffffffffu, q, off);
    }
    __shared__ float sh1[8], sh2[8];
    __shared__ float smu, srstd;
    int warp = tid >> 5, lane = tid & 31;
    if (lane == 0) { sh1[warp] = s; sh2[warp] = q; }
    __syncthreads();
    if (tid == 0) {
        float S = 0.0f, Q = 0.0f;
#pragma unroll
        for (int w = 0; w < 8; w++) { S += sh1[w]; Q += sh2[w]; }
        float mu = S * (1.0f / DMODEL);
        float var = Q * (1.0f / DMODEL) - mu * mu;
        smu = mu;
        srstd = rsqrtf(var + 1e-6f);
    }
    __syncthreads();
    float mu = smu, rstd = srstd;

    float4 gv = ((const float4*)gamma)[tid];
    float4 bv = ((const float4*)beta)[tid];
    float4 ov;
    ov.x = (xv.x - mu) * rstd * gv.x + bv.x;
    ov.y = (xv.y - mu) * rstd * gv.y + bv.y;
    ov.z = (xv.z - mu) * rstd * gv.z + bv.z;
    ov.w = (xv.w - mu) * rstd * gv.w + bv.w;
    ((float4*)(out + (size_t)row * DMODEL))[tid] = ov;
}

// ---------------- launch ----------------
extern "C" void kernel_launch(void* const* d_in, const int* in_sizes, int n_in,
                              void* d_out, int out_size)
{
    const float* q    = (const float*)d_in[0];
    const float* k    = (const float*)d_in[1];
    const float* v    = (const float*)d_in[2];
    const int*   mask = (const int*)d_in[3];
    const float* Wq   = (const float*)d_in[4];
    const float* bq   = (const float*)d_in[5];
    const float* Wout = (const float*)d_in[6];
    const float* bout = (const float*)d_in[7];
    const float* gamma = (const float*)d_in[8];
    const float* beta  = (const float*)d_in[9];

    float* outp = (float*)d_out;
    float* wptr = (float*)0;
    const long long need = (long long)MROWS * DMODEL + (long long)BHEADS * SEQ * SEQ;
    if ((long long)out_size >= need) wptr = outp + (size_t)MROWS * DMODEL;

    static int attr_done = 0;
    if (!attr_done) {
        cudaFuncSetAttribute(gemm_cp<0>, cudaFuncAttributeMaxDynamicSharedMemorySize, GEMM_SMEM);
        cudaFuncSetAttribute(gemm_cp<1>, cudaFuncAttributeMaxDynamicSharedMemorySize, GEMM_SMEM);
        cudaFuncSetAttribute(scores_cp, cudaFuncAttributeMaxDynamicSharedMemorySize, SCORES_SMEM);
        cudaFuncSetAttribute(av_cp, cudaFuncAttributeMaxDynamicSharedMemorySize, AV_SMEM);
        attr_done = 1;
    }

    init_den_kernel<<<64, 1024>>>();

    // fused q/k/v projections (same weight), grid.z = 3
    gemm_cp<0><<<dim3(DMODEL / 128, MROWS / 128, 3), 256, GEMM_SMEM>>>(
        q, k, v, Wq, bq, (const float*)0);

    scores_cp<<<dim3(SEQ / 128, SEQ / 128, BHEADS), 256, SCORES_SMEM>>>(mask);

    av_cp<<<dim3(SEQ / 128, BHEADS), 256, AV_SMEM>>>(wptr);

    gemm_cp<1><<<dim3(DMODEL / 128, MROWS / 128, 1), 256, GEMM_SMEM>>>(
        (const float*)0, (const float*)0, (const float*)0, Wout, bout, q);

    ln_kernel<<<MROWS, 256>>>(gamma, beta, outp);
}